// round 11
// baseline (speedup 1.0000x reference)
#include <cuda_runtime.h>

// D fixed by the problem (256 floats per row).
#define D     256
#define TPB   128
#define WPB   (TPB / 32)
#define NBLK  1216            // 152 SMs x 8 resident blocks: one persistent wave

// Per-block partial sums (every slot written every call -> no zeroing needed).
__device__ double   d_part[NBLK];
// Completion counter: 0 at start, last block resets it -> replay-deterministic.
__device__ unsigned d_count;

__device__ __forceinline__ float dot4(float4 a, float4 b) {
    return a.x * b.x + a.y * b.y + a.z * b.z + a.w * b.w;
}

// Warp-reduce TWO values with 7 shuffles (vs 10): xor-16 exchange packs a's
// half-sums into lanes 0-15 and b's into 16-31, 4 butterfly stages finish
// both, one unpack returns (sumA, sumB) to every lane. Same add tree as the
// plain 5-stage butterfly (offsets 16,8,4,2,1) -> bit-identical sums.
__device__ __forceinline__ float2 wred2(float a, float b, int lane) {
    const float ao = __shfl_xor_sync(0xffffffffu, a, 16);
    const float bo = __shfl_xor_sync(0xffffffffu, b, 16);
    const bool lo = (lane & 16) == 0;
    float z = lo ? (a + ao) : (b + bo);
#pragma unroll
    for (int off = 8; off > 0; off >>= 1)
        z += __shfl_xor_sync(0xffffffffu, z, off);
    const float w = __shfl_xor_sync(0xffffffffu, z, 16);
    return make_float2(lo ? z : w, lo ? w : z);
}

// ---------------------------------------------------------------------------
// Persistent single-wave kernel, rows processed in pairs per warp.
//   total = sum_i  dot(h1_i, g2_b)*ginv(h1_i)*ginv(g2_b)
//               +  dot(h2_i, g1_b)*ginv(h2_i)*ginv(g1_b),   b = batch[i]
// batch is sorted: the two 1 KB g rows live in registers, reloaded only on
// (rare) b change; inverse norms computed inline then. 8 LDG.128 batched per
// pair; packed reductions (28 SHFL/pair) shrink the load-free dead phase.
// ---------------------------------------------------------------------------
__global__ void __launch_bounds__(TPB, 8)
main_k(const float* __restrict__ h1, const float* __restrict__ h2,
       const float* __restrict__ g1, const float* __restrict__ g2,
       const int*   __restrict__ batch, float* __restrict__ out,
       int N, int G)
{
    const int lane  = threadIdx.x & 31;
    const int wid   = threadIdx.x >> 5;
    const int gwarp = blockIdx.x * WPB + wid;
    const int nw    = gridDim.x * WPB;

    const int per = (N + nw - 1) / nw;
    const int i0  = gwarp * per;
    const int i1  = min(N, i0 + per);

    double acc = 0.0;

    int   bcur = -1;
    float gi1 = 0.f, gi2 = 0.f;               // lane-uniform inverse norms
    float4 fg0, fg1, cg0, cg1;                // cached g1/g2 rows (lane slice)
    fg0 = fg1 = cg0 = cg1 = make_float4(0.f, 0.f, 0.f, 0.f);

#define RELOAD_G(B)                                                          \
    do {                                                                     \
        bcur = (B);                                                          \
        const float4* pg1 = reinterpret_cast<const float4*>(g1 + (size_t)bcur * D); \
        const float4* pg2 = reinterpret_cast<const float4*>(g2 + (size_t)bcur * D); \
        fg0 = pg1[lane]; fg1 = pg1[lane + 32];                               \
        cg0 = pg2[lane]; cg1 = pg2[lane + 32];                               \
        float2 sg = wred2(dot4(fg0, fg0) + dot4(fg1, fg1),                   \
                          dot4(cg0, cg0) + dot4(cg1, cg1), lane);            \
        gi1 = rsqrtf(fmaxf(sg.x, 1e-24f));                                   \
        gi2 = rsqrtf(fmaxf(sg.y, 1e-24f));                                   \
    } while (0)

    int i = i0;
    for (; i + 2 <= i1; i += 2) {
        const int ba = batch[i];
        const int bb = batch[i + 1];          // sorted: ba <= bb

        // Batch all 8 h loads up front (MLP=8, evict-first streaming).
        const float4* pa1 = reinterpret_cast<const float4*>(h1 + (size_t)i * D);
        const float4* pa2 = reinterpret_cast<const float4*>(h2 + (size_t)i * D);
        const float4* pb1 = reinterpret_cast<const float4*>(h1 + (size_t)(i + 1) * D);
        const float4* pb2 = reinterpret_cast<const float4*>(h2 + (size_t)(i + 1) * D);
        float4 a0 = __ldcs(pa1 + lane), a1 = __ldcs(pa1 + lane + 32);
        float4 e0 = __ldcs(pa2 + lane), e1 = __ldcs(pa2 + lane + 32);
        float4 b0 = __ldcs(pb1 + lane), b1 = __ldcs(pb1 + lane + 32);
        float4 f0 = __ldcs(pb2 + lane), f1 = __ldcs(pb2 + lane + 32);

        if (ba != bcur) RELOAD_G(ba);         // warp-uniform, rare
        const float gia1 = gi1, gia2 = gi2;   // snapshot for row a

        const float da1 = dot4(a0, cg0) + dot4(a1, cg1);
        const float sa1 = dot4(a0, a0)  + dot4(a1, a1);
        const float da2 = dot4(e0, fg0) + dot4(e1, fg1);
        const float sa2 = dot4(e0, e0)  + dot4(e1, e1);

        if (bb != bcur) RELOAD_G(bb);         // row a's dots already formed

        const float db1 = dot4(b0, cg0) + dot4(b1, cg1);
        const float sb1 = dot4(b0, b0)  + dot4(b1, b1);
        const float db2 = dot4(f0, fg0) + dot4(f1, fg1);
        const float sb2 = dot4(f0, f0)  + dot4(f1, f1);

        // 4 packed reductions, independent -> interleaved by ptxas.
        const float2 ra1 = wred2(da1, sa1, lane);
        const float2 ra2 = wred2(da2, sa2, lane);
        const float2 rb1 = wred2(db1, sb1, lane);
        const float2 rb2 = wred2(db2, sb2, lane);

        const float va = ra1.x * rsqrtf(fmaxf(ra1.y, 1e-24f)) * gia2
                       + ra2.x * rsqrtf(fmaxf(ra2.y, 1e-24f)) * gia1;
        const float vb = rb1.x * rsqrtf(fmaxf(rb1.y, 1e-24f)) * gi2
                       + rb2.x * rsqrtf(fmaxf(rb2.y, 1e-24f)) * gi1;
        acc += (double)va;
        acc += (double)vb;
    }

    if (i < i1) {                              // odd remainder row
        const int b = batch[i];
        const float4* ph1 = reinterpret_cast<const float4*>(h1 + (size_t)i * D);
        const float4* ph2 = reinterpret_cast<const float4*>(h2 + (size_t)i * D);
        float4 a0 = __ldcs(ph1 + lane), a1 = __ldcs(ph1 + lane + 32);
        float4 e0 = __ldcs(ph2 + lane), e1 = __ldcs(ph2 + lane + 32);

        if (b != bcur) RELOAD_G(b);

        const float2 r1 = wred2(dot4(a0, cg0) + dot4(a1, cg1),
                                dot4(a0, a0)  + dot4(a1, a1), lane);
        const float2 r2 = wred2(dot4(e0, fg0) + dot4(e1, fg1),
                                dot4(e0, e0)  + dot4(e1, e1), lane);
        const float v = r1.x * rsqrtf(fmaxf(r1.y, 1e-24f)) * gi2
                      + r2.x * rsqrtf(fmaxf(r2.y, 1e-24f)) * gi1;
        acc += (double)v;
    }
#undef RELOAD_G

    // ---- block-level partial ----
    __shared__ double sred[WPB];
    __shared__ bool   is_last;
    if (lane == 0) sred[wid] = acc;
    __syncthreads();
    if (threadIdx.x == 0) {
        double t = 0.0;
#pragma unroll
        for (int w = 0; w < WPB; ++w) t += sred[w];
        d_part[blockIdx.x] = t;
        __threadfence();
        unsigned prev = atomicAdd(&d_count, 1u);
        is_last = (prev == (unsigned)(NBLK - 1));
    }
    __syncthreads();

    // ---- last block: fixed-order deterministic final reduction ----
    if (is_last) {
        __shared__ double s[TPB];
        double t = 0.0;
        for (int k = threadIdx.x; k < NBLK; k += TPB)
            t += __ldcg(&d_part[k]);
        s[threadIdx.x] = t;
        __syncthreads();
#pragma unroll
        for (int off = TPB / 2; off > 0; off >>= 1) {
            if (threadIdx.x < off) s[threadIdx.x] += s[threadIdx.x + off];
            __syncthreads();
        }
        if (threadIdx.x == 0) {
            *out = (float)(s[0] / (double)G);
            d_count = 0;                       // reset for next graph replay
        }
    }
}

extern "C" void kernel_launch(void* const* d_in, const int* in_sizes, int n_in,
                              void* d_out, int out_size)
{
    const float* h1    = (const float*)d_in[0];
    const float* h2    = (const float*)d_in[1];
    const float* g1    = (const float*)d_in[2];
    const float* g2    = (const float*)d_in[3];
    const int*   batch = (const int*)d_in[4];   // jax default int32 (x64 disabled)

    const int N = in_sizes[4];          // rows in h1/h2
    const int G = in_sizes[2] / D;      // rows in g1/g2

    main_k<<<NBLK, TPB>>>(h1, h2, g1, g2, batch, (float*)d_out, N, G);
}

// round 12
// speedup vs baseline: 1.0420x; 1.0420x over previous
#include <cuda_runtime.h>

// D fixed by the problem (256 floats per row).
#define D     256
#define TPB   128
#define WPB   (TPB / 32)
#define NBLK  912             // 152 SMs x 6 resident blocks: one persistent wave

// Per-block partial sums (every slot written every call -> no zeroing needed).
__device__ double   d_part[NBLK];
// Completion counter: 0 at start, last block resets it -> replay-deterministic.
__device__ unsigned d_count;

__device__ __forceinline__ float dot4(float4 a, float4 b) {
    return a.x * b.x + a.y * b.y + a.z * b.z + a.w * b.w;
}

// ---------------------------------------------------------------------------
// Persistent single-wave kernel, SOFTWARE-PIPELINED row pairs per warp:
//   next pair's 8 LDG.128 are issued after the current pair's dot-products
//   (which free the data registers) and BEFORE the shuffle-reduce phase, so
//   loads stay in flight through the whole reduction.
//   total = sum_i  dot(h1_i, g2_b)*ginv(h1_i)*ginv(g2_b)
//               +  dot(h2_i, g1_b)*ginv(h2_i)*ginv(g1_b),   b = batch[i]
// batch is sorted: the two 1 KB g rows live in registers, reloaded only on
// (rare) b change; inverse norms computed inline then.
// ---------------------------------------------------------------------------
__global__ void __launch_bounds__(TPB, 6)
main_k(const float* __restrict__ h1, const float* __restrict__ h2,
       const float* __restrict__ g1, const float* __restrict__ g2,
       const int*   __restrict__ batch, float* __restrict__ out,
       int N, int G)
{
    const int lane  = threadIdx.x & 31;
    const int wid   = threadIdx.x >> 5;
    const int gwarp = blockIdx.x * WPB + wid;
    const int nw    = gridDim.x * WPB;

    const int per = (N + nw - 1) / nw;
    const int i0  = gwarp * per;
    const int i1  = min(N, i0 + per);

    double acc = 0.0;

    int   bcur = -1;
    float gi1 = 0.f, gi2 = 0.f;               // lane-uniform inverse norms
    float4 fg0, fg1, cg0, cg1;                // cached g1/g2 rows (lane slice)
    fg0 = fg1 = cg0 = cg1 = make_float4(0.f, 0.f, 0.f, 0.f);

#define RELOAD_G(B)                                                          \
    do {                                                                     \
        bcur = (B);                                                          \
        const float4* pg1 = reinterpret_cast<const float4*>(g1 + (size_t)bcur * D); \
        const float4* pg2 = reinterpret_cast<const float4*>(g2 + (size_t)bcur * D); \
        fg0 = pg1[lane]; fg1 = pg1[lane + 32];                               \
        cg0 = pg2[lane]; cg1 = pg2[lane + 32];                               \
        float sg1 = dot4(fg0, fg0) + dot4(fg1, fg1);                         \
        float sg2 = dot4(cg0, cg0) + dot4(cg1, cg1);                         \
        _Pragma("unroll")                                                    \
        for (int off = 16; off > 0; off >>= 1) {                             \
            sg1 += __shfl_xor_sync(0xffffffffu, sg1, off);                   \
            sg2 += __shfl_xor_sync(0xffffffffu, sg2, off);                   \
        }                                                                    \
        gi1 = rsqrtf(fmaxf(sg1, 1e-24f));                                    \
        gi2 = rsqrtf(fmaxf(sg2, 1e-24f));                                    \
    } while (0)

#define LOAD_PAIR(I)                                                         \
    do {                                                                     \
        const float4* pa1 = reinterpret_cast<const float4*>(h1 + (size_t)(I) * D);       \
        const float4* pa2 = reinterpret_cast<const float4*>(h2 + (size_t)(I) * D);       \
        const float4* pb1 = reinterpret_cast<const float4*>(h1 + (size_t)((I) + 1) * D); \
        const float4* pb2 = reinterpret_cast<const float4*>(h2 + (size_t)((I) + 1) * D); \
        a0 = __ldcs(pa1 + lane); a1 = __ldcs(pa1 + lane + 32);               \
        e0 = __ldcs(pa2 + lane); e1 = __ldcs(pa2 + lane + 32);               \
        b0 = __ldcs(pb1 + lane); b1 = __ldcs(pb1 + lane + 32);               \
        f0 = __ldcs(pb2 + lane); f1 = __ldcs(pb2 + lane + 32);               \
    } while (0)

    float4 a0, a1, e0, e1, b0, b1, f0, f1;
    int i  = i0;
    int ba = 0, bb = 0;
    bool have = (i + 1 < i1);                 // a full pair exists
    if (have) {
        ba = batch[i]; bb = batch[i + 1];
        LOAD_PAIR(i);                         // prologue
    }

    while (have) {
        const int  ni    = i + 2;
        const bool nhave = (ni + 1 < i1);

        // ---- consume current pair's data into 8 dot scalars ----
        if (ba != bcur) RELOAD_G(ba);         // warp-uniform, rare
        const float gia1 = gi1, gia2 = gi2;   // snapshot for row a

        float da1 = dot4(a0, cg0) + dot4(a1, cg1);
        float sa1 = dot4(a0, a0)  + dot4(a1, a1);
        float da2 = dot4(e0, fg0) + dot4(e1, fg1);
        float sa2 = dot4(e0, e0)  + dot4(e1, e1);

        if (bb != bcur) RELOAD_G(bb);         // sorted: ba <= bb

        float db1 = dot4(b0, cg0) + dot4(b1, cg1);
        float sb1 = dot4(b0, b0)  + dot4(b1, b1);
        float db2 = dot4(f0, fg0) + dot4(f1, fg1);
        float sb2 = dot4(f0, f0)  + dot4(f1, f1);

        // ---- issue NEXT pair's loads: in flight during the reductions ----
        int nba = ba, nbb = bb;
        if (nhave) {
            nba = batch[ni]; nbb = batch[ni + 1];
            LOAD_PAIR(ni);
        }

        // ---- 8 interleaved butterfly chains (loads overlapping) ----
#pragma unroll
        for (int off = 16; off > 0; off >>= 1) {
            da1 += __shfl_xor_sync(0xffffffffu, da1, off);
            sa1 += __shfl_xor_sync(0xffffffffu, sa1, off);
            da2 += __shfl_xor_sync(0xffffffffu, da2, off);
            sa2 += __shfl_xor_sync(0xffffffffu, sa2, off);
            db1 += __shfl_xor_sync(0xffffffffu, db1, off);
            sb1 += __shfl_xor_sync(0xffffffffu, sb1, off);
            db2 += __shfl_xor_sync(0xffffffffu, db2, off);
            sb2 += __shfl_xor_sync(0xffffffffu, sb2, off);
        }

        const float va = da1 * rsqrtf(fmaxf(sa1, 1e-24f)) * gia2
                       + da2 * rsqrtf(fmaxf(sa2, 1e-24f)) * gia1;
        const float vb = db1 * rsqrtf(fmaxf(sb1, 1e-24f)) * gi2
                       + db2 * rsqrtf(fmaxf(sb2, 1e-24f)) * gi1;
        acc += (double)va;
        acc += (double)vb;

        i = ni; ba = nba; bb = nbb; have = nhave;
    }

    if (i < i1) {                              // odd remainder row
        const int b = batch[i];
        const float4* ph1 = reinterpret_cast<const float4*>(h1 + (size_t)i * D);
        const float4* ph2 = reinterpret_cast<const float4*>(h2 + (size_t)i * D);
        float4 x0 = __ldcs(ph1 + lane), x1 = __ldcs(ph1 + lane + 32);
        float4 y0 = __ldcs(ph2 + lane), y1 = __ldcs(ph2 + lane + 32);

        if (b != bcur) RELOAD_G(b);

        float d1 = dot4(x0, cg0) + dot4(x1, cg1);
        float s1 = dot4(x0, x0)  + dot4(x1, x1);
        float d2 = dot4(y0, fg0) + dot4(y1, fg1);
        float s2 = dot4(y0, y0)  + dot4(y1, y1);
#pragma unroll
        for (int off = 16; off > 0; off >>= 1) {
            d1 += __shfl_xor_sync(0xffffffffu, d1, off);
            s1 += __shfl_xor_sync(0xffffffffu, s1, off);
            d2 += __shfl_xor_sync(0xffffffffu, d2, off);
            s2 += __shfl_xor_sync(0xffffffffu, s2, off);
        }
        const float v = d1 * rsqrtf(fmaxf(s1, 1e-24f)) * gi2
                      + d2 * rsqrtf(fmaxf(s2, 1e-24f)) * gi1;
        acc += (double)v;
    }
#undef LOAD_PAIR
#undef RELOAD_G

    // ---- block-level partial ----
    __shared__ double sred[WPB];
    __shared__ bool   is_last;
    if (lane == 0) sred[wid] = acc;
    __syncthreads();
    if (threadIdx.x == 0) {
        double t = 0.0;
#pragma unroll
        for (int w = 0; w < WPB; ++w) t += sred[w];
        d_part[blockIdx.x] = t;
        __threadfence();
        unsigned prev = atomicAdd(&d_count, 1u);
        is_last = (prev == (unsigned)(NBLK - 1));
    }
    __syncthreads();

    // ---- last block: fixed-order deterministic final reduction ----
    if (is_last) {
        __shared__ double s[TPB];
        double t = 0.0;
        for (int k = threadIdx.x; k < NBLK; k += TPB)
            t += __ldcg(&d_part[k]);
        s[threadIdx.x] = t;
        __syncthreads();
#pragma unroll
        for (int off = TPB / 2; off > 0; off >>= 1) {
            if (threadIdx.x < off) s[threadIdx.x] += s[threadIdx.x + off];
            __syncthreads();
        }
        if (threadIdx.x == 0) {
            *out = (float)(s[0] / (double)G);
            d_count = 0;                       // reset for next graph replay
        }
    }
}

extern "C" void kernel_launch(void* const* d_in, const int* in_sizes, int n_in,
                              void* d_out, int out_size)
{
    const float* h1    = (const float*)d_in[0];
    const float* h2    = (const float*)d_in[1];
    const float* g1    = (const float*)d_in[2];
    const float* g2    = (const float*)d_in[3];
    const int*   batch = (const int*)d_in[4];   // jax default int32 (x64 disabled)

    const int N = in_sizes[4];          // rows in h1/h2
    const int G = in_sizes[2] / D;      // rows in g1/g2

    main_k<<<NBLK, TPB>>>(h1, h2, g1, g2, batch, (float*)d_out, N, G);
}